// round 13
// baseline (speedup 1.0000x reference)
#include <cuda_runtime.h>
#include <cstdint>

// FullAttention "neighbour": B=8,V=8,L=768,H=8,E=64,p=6 -> 65,536 independent
// 6x6x64 attention problems. Two groups per warp-half (16 lanes, float4/lane).
// R6: 4-way packed butterflies (45 SHFL + 9 EX2 per lane for 36 scores).
// R12 (re-run; previous bench hit an infra failure): software-pipelined
// streaming. Each warp processes NITER=4 stages (2 groups each) with a
// depth-2 cp.async pipeline staging Q,K,V in smem. RACE FIX vs R11: vr[] is
// loaded from smem BEFORE prefetch(t+2) is issued -- program order
// guarantees the stage-(t+2) cp.async writes to the same buffer cannot land
// before the stage-t reads. 2-warp blocks, 36KB static smem -> 6 blocks/SM
// = 12 warps (low occ BY DESIGN; DRAM saturation comes from the steady
// pipeline, not warp count).

namespace {
constexpr int Bq = 8, Vq = 8, Lq = 768, Hq = 8, Eq = 64;
constexpr int NGROUPS = 128;
constexpr int WARPS_PER_BLOCK = 2;
constexpr int NITER = 4;                                 // stages per warp
constexpr int ROWSTRIDE = Hq * Eq;                       // 512
constexpr float SCALE2 = 0.125f * 1.4426950408889634f;   // scale * log2(e)
constexpr unsigned FULL = 0xffffffffu;
// smem: [buf2][warp2][half2] slots of [tensor3][row6][lane16] float4
constexpr int SLOT_F4 = 3 * 6 * 16;                      // 288 float4 per slot
constexpr int SMEM_F4 = 2 * 2 * 2 * SLOT_F4;             // 2304 float4 = 36 KB
}

__device__ __forceinline__ float dp4(const float4& x, const float4& y) {
    return x.x * y.x + x.y * y.y + x.z * y.z + x.w * y.w;
}

// Reduce 4 independent per-lane partials over each 16-lane half.
// Result lands in 4-lane group (hi8,hi4)=(0,0)->a (0,1)->b (1,0)->c (1,1)->d,
// replicated within the group. Source lane for value v: l16 = 8*(v>>1)+4*(v&1).
__device__ __forceinline__ float quadReduce(float a, float b, float c, float d,
                                            bool hi8, bool hi4) {
    float u = (hi8 ? c : a) + __shfl_xor_sync(FULL, hi8 ? a : c, 8);
    float v = (hi8 ? d : b) + __shfl_xor_sync(FULL, hi8 ? b : d, 8);
    float w = (hi4 ? v : u) + __shfl_xor_sync(FULL, hi4 ? u : v, 4);
    w += __shfl_xor_sync(FULL, w, 2);
    w += __shfl_xor_sync(FULL, w, 1);
    return w;
}

__global__ __launch_bounds__(WARPS_PER_BLOCK * 32)
void neighbour_attn_kernel(const float* __restrict__ Q,
                           const float* __restrict__ K,
                           const float* __restrict__ V,
                           float* __restrict__ O)
{
    __shared__ float4 sm[SMEM_F4];

    const int warp = threadIdx.x >> 5;
    const int lane = threadIdx.x & 31;
    const int half = lane >> 4;
    const int l16  = lane & 15;
    const bool hi8 = (l16 & 8) != 0;
    const bool hi4 = (l16 & 4) != 0;

    // this warp-half covers gids wbase + 2*t for t in [0, NITER)
    const int wbase = (blockIdx.x * WARPS_PER_BLOCK + warp) * (2 * NITER) + half;

    // per-(warp,half) smem slot bases for the two buffers, in bytes, at this
    // lane's float4 within row 0 of each tensor
    const uint32_t smBase = (uint32_t)__cvta_generic_to_shared(sm);
    uint32_t slotB[2];
#pragma unroll
    for (int bf = 0; bf < 2; bf++)
        slotB[bf] = smBase + (((bf * 2 + warp) * 2 + half) * SLOT_F4 + l16) * 16;

    // compute the 6 global row offsets (in floats) for stage t
    auto rowOffsets = [&](int t, int o[6]) {
        const int gid = wbase + 2 * t;
        const int g  = gid & (NGROUPS - 1);
        const int h  = (gid >> 7) & (Hq - 1);
        const int vv = (gid >> 10) & (Vq - 1);
        const int b  = gid >> 13;
        const int base = ((b * Vq + vv) * Lq) * ROWSTRIDE + h * Eq + 4 * l16;
        const int li0  = 3 + g * 6;          // g=127 wraps 765..770 -> mod 768
#pragma unroll
        for (int i = 0; i < 6; i++) {
            int li = li0 + i; if (li >= Lq) li -= Lq;
            o[i] = base + li * ROWSTRIDE;
        }
    };

    // prefetch stage t into buffer t&1 (18 cp.async per lane) + commit
    auto prefetch = [&](int t) {
        int o[6];
        rowOffsets(t, o);
        const uint32_t s = slotB[t & 1];
#pragma unroll
        for (int i = 0; i < 6; i++) {
            asm volatile("cp.async.cg.shared.global [%0], [%1], 16;\n"
                         :: "r"(s + (0 * 96 + i * 16) * 16), "l"(Q + o[i]) : "memory");
            asm volatile("cp.async.cg.shared.global [%0], [%1], 16;\n"
                         :: "r"(s + (1 * 96 + i * 16) * 16), "l"(K + o[i]) : "memory");
            asm volatile("cp.async.cg.shared.global [%0], [%1], 16;\n"
                         :: "r"(s + (2 * 96 + i * 16) * 16), "l"(V + o[i]) : "memory");
        }
        asm volatile("cp.async.commit_group;\n" ::: "memory");
    };

    prefetch(0);
    prefetch(1);

#pragma unroll
    for (int t = 0; t < NITER; t++) {
        if (t == NITER - 1) {
            asm volatile("cp.async.wait_group 0;\n" ::: "memory");
        } else {
            asm volatile("cp.async.wait_group 1;\n" ::: "memory");
        }
        // each lane reads only bytes its own cp.async wrote -> no syncwarp

        int o[6];
        rowOffsets(t, o);
        const float4* p = (const float4*)(sm) +
                          (((size_t)(t & 1) * 2 + warp) * 2 + half) * SLOT_F4 + l16;

        // ---- read ALL of stage t's data (q,k,v) BEFORE any overwrite can be
        // issued: vr must precede prefetch(t+2), which reuses this buffer.
        float4 qr[6], kr[6], vr[6];
#pragma unroll
        for (int i = 0; i < 6; i++) {
            qr[i] = p[0 * 96 + i * 16];
            kr[i] = p[1 * 96 + i * 16];
            vr[i] = p[2 * 96 + i * 16];
        }

        // now safe: stage t+2 overwrites buf t&1, all reads already done
        if (t + 2 < NITER) prefetch(t + 2);

        // packed score reductions + EX2 on the owned score.
        // Quads 0..5: (row i, j=0..3). Quads 6..8: (rows 2r,2r+1, j=4,5).
        float eq[9];
#pragma unroll
        for (int i = 0; i < 6; i++) {
            float w = quadReduce(dp4(qr[i], kr[0]), dp4(qr[i], kr[1]),
                                 dp4(qr[i], kr[2]), dp4(qr[i], kr[3]), hi8, hi4);
            eq[i] = exp2f(w * SCALE2);
        }
#pragma unroll
        for (int r = 0; r < 3; r++) {
            float w = quadReduce(dp4(qr[2 * r], kr[4]), dp4(qr[2 * r], kr[5]),
                                 dp4(qr[2 * r + 1], kr[4]), dp4(qr[2 * r + 1], kr[5]),
                                 hi8, hi4);
            eq[6 + r] = exp2f(w * SCALE2);
        }

        // per row: broadcast the 6 e's from static source lanes, accumulate
        // denominator + A*V, normalize, store coalesced float4.
#pragma unroll
        for (int i = 0; i < 6; i++) {
            float e[6];
#pragma unroll
            for (int j = 0; j < 4; j++)   // quad i, value j -> lane 8*(j>>1)+4*(j&1)
                e[j] = __shfl_sync(FULL, eq[i], 8 * (j >> 1) + 4 * (j & 1), 16);
            {
                const int qp = 6 + (i >> 1);
                e[4] = __shfl_sync(FULL, eq[qp], 8 * (i & 1), 16);
                e[5] = __shfl_sync(FULL, eq[qp], 8 * (i & 1) + 4, 16);
            }
            float sum = 0.f;
            float4 acc = make_float4(0.f, 0.f, 0.f, 0.f);
#pragma unroll
            for (int j = 0; j < 6; j++) {
                sum += e[j];
                acc.x = fmaf(e[j], vr[j].x, acc.x);
                acc.y = fmaf(e[j], vr[j].y, acc.y);
                acc.z = fmaf(e[j], vr[j].z, acc.z);
                acc.w = fmaf(e[j], vr[j].w, acc.w);
            }
            const float inv = __frcp_rn(sum);
            acc.x *= inv; acc.y *= inv; acc.z *= inv; acc.w *= inv;
            *reinterpret_cast<float4*>(O + o[i]) = acc;
        }
    }
}

extern "C" void kernel_launch(void* const* d_in, const int* in_sizes, int n_in,
                              void* d_out, int out_size)
{
    const float* Q = (const float*)d_in[0];
    const float* K = (const float*)d_in[1];
    const float* V = (const float*)d_in[2];
    float* O = (float*)d_out;

    const int total_groups = Bq * Vq * Hq * NGROUPS;                  // 65536
    const int blocks = total_groups / (WARPS_PER_BLOCK * 2 * NITER);  // 4096
    neighbour_attn_kernel<<<blocks, WARPS_PER_BLOCK * 32>>>(Q, K, V, O);
}

// round 14
// speedup vs baseline: 1.0146x; 1.0146x over previous
#include <cuda_runtime.h>
#include <cstdint>

// FullAttention "neighbour": B=8,V=8,L=768,H=8,E=64,p=6 -> 65,536 independent
// 6x6x64 attention problems. Two groups per warp (16-lane halves); lane owns
// 4 head-dim columns (float4).
// R6: 4-way packed butterflies (45 SHFL + 9 EX2 per lane for 36 scores).
// R10: V prefetched via cp.async into smem (no registers held in flight).
// R14: gid decomposition reordered to b|v|g|h (h FASTEST). The two halves of
// a warp now cover the same 6 tokens at adjacent h -> one contiguous 512B
// load per row per warp; a 256-thread block streams a contiguous 24KB range
// per tensor. Pure work-permutation targeting the DRAM-efficiency ceiling
// (77-79% across three prior designs regardless of occupancy/pipelining).

namespace {
constexpr int Bq = 8, Vq = 8, Lq = 768, Hq = 8, Eq = 64;
constexpr int NGROUPS = 128;
constexpr int WARPS_PER_BLOCK = 8;
constexpr int ROWSTRIDE = Hq * Eq;                       // 512
constexpr float SCALE2 = 0.125f * 1.4426950408889634f;   // scale * log2(e)
constexpr unsigned FULL = 0xffffffffu;
}

__device__ __forceinline__ float dp4(const float4& x, const float4& y) {
    return x.x * y.x + x.y * y.y + x.z * y.z + x.w * y.w;
}

// Reduce 4 independent per-lane partials over each 16-lane half.
// Result lands in 4-lane group (hi8,hi4)=(0,0)->a (0,1)->b (1,0)->c (1,1)->d,
// replicated within the group. Source lane for value v: l16 = 8*(v>>1)+4*(v&1).
__device__ __forceinline__ float quadReduce(float a, float b, float c, float d,
                                            bool hi8, bool hi4) {
    float u = (hi8 ? c : a) + __shfl_xor_sync(FULL, hi8 ? a : c, 8);
    float v = (hi8 ? d : b) + __shfl_xor_sync(FULL, hi8 ? b : d, 8);
    float w = (hi4 ? v : u) + __shfl_xor_sync(FULL, hi4 ? u : v, 4);
    w += __shfl_xor_sync(FULL, w, 2);
    w += __shfl_xor_sync(FULL, w, 1);
    return w;
}

__global__ __launch_bounds__(WARPS_PER_BLOCK * 32, 4)
void neighbour_attn_kernel(const float* __restrict__ Q,
                           const float* __restrict__ K,
                           const float* __restrict__ V,
                           float* __restrict__ O)
{
    // V staging: [warp][half][row][lane16] float4 = 24 KB per block
    __shared__ float4 vsm[WARPS_PER_BLOCK * 2 * 6 * 16];

    const int warp = threadIdx.x >> 5;
    const int lane = threadIdx.x & 31;
    const int half = lane >> 4;
    const int l16  = lane & 15;
    const bool hi8 = (l16 & 8) != 0;
    const bool hi4 = (l16 & 4) != 0;

    const int gid = (blockIdx.x * WARPS_PER_BLOCK + warp) * 2 + half;

    // R14 decomposition: h fastest -> contiguous streaming per block
    const int h  = gid & (Hq - 1);
    const int g  = (gid >> 3) & (NGROUPS - 1);
    const int vv = (gid >> 10) & (Vq - 1);
    const int b  = gid >> 13;

    const int base = ((b * Vq + vv) * Lq) * ROWSTRIDE + h * Eq + 4 * l16;
    const int li0  = 3 + g * 6;          // g=127 wraps 765..770 -> mod 768

    int o[6];
#pragma unroll
    for (int i = 0; i < 6; i++) {
        int li = li0 + i; if (li >= Lq) li -= Lq;
        o[i] = base + li * ROWSTRIDE;
    }

    // ---- phase 1a: Q,K LDGs (needed first)
    float4 qr[6], kr[6];
#pragma unroll
    for (int i = 0; i < 6; i++) {
        qr[i] = *reinterpret_cast<const float4*>(Q + o[i]);
        kr[i] = *reinterpret_cast<const float4*>(K + o[i]);
    }

    // ---- phase 1b: V prefetch via cp.async (no registers held in flight)
    const int vidx = ((warp * 2 + half) * 6) * 16 + l16;     // float4 index
    const uint32_t sv0 = (uint32_t)__cvta_generic_to_shared(&vsm[vidx]);
#pragma unroll
    for (int i = 0; i < 6; i++) {
        asm volatile("cp.async.cg.shared.global [%0], [%1], 16;\n"
                     :: "r"(sv0 + i * 16 * 16), "l"(V + o[i]) : "memory");
    }
    asm volatile("cp.async.commit_group;\n" ::: "memory");

    // ---- phase 2: packed score reductions + EX2 on the owned score.
    // Quads 0..5: (row i, j=0..3). Quads 6..8: (rows 2r,2r+1, j=4,5).
    float eq[9];
#pragma unroll
    for (int i = 0; i < 6; i++) {
        float w = quadReduce(dp4(qr[i], kr[0]), dp4(qr[i], kr[1]),
                             dp4(qr[i], kr[2]), dp4(qr[i], kr[3]), hi8, hi4);
        eq[i] = exp2f(w * SCALE2);
    }
#pragma unroll
    for (int r = 0; r < 3; r++) {
        float w = quadReduce(dp4(qr[2 * r], kr[4]), dp4(qr[2 * r], kr[5]),
                             dp4(qr[2 * r + 1], kr[4]), dp4(qr[2 * r + 1], kr[5]),
                             hi8, hi4);
        eq[6 + r] = exp2f(w * SCALE2);
    }

    // ---- phase 3: V from smem (each lane reads the 16B it issued itself)
    asm volatile("cp.async.wait_group 0;\n" ::: "memory");
    float4 vr[6];
#pragma unroll
    for (int i = 0; i < 6; i++)
        vr[i] = vsm[vidx + i * 16];

    // ---- phase 4: per row, broadcast the 6 e's from static source lanes,
    // accumulate denominator + A*V, normalize, store coalesced float4.
#pragma unroll
    for (int i = 0; i < 6; i++) {
        float e[6];
#pragma unroll
        for (int j = 0; j < 4; j++)      // quad i, value j -> lane 8*(j>>1)+4*(j&1)
            e[j] = __shfl_sync(FULL, eq[i], 8 * (j >> 1) + 4 * (j & 1), 16);
        {
            const int qp = 6 + (i >> 1); // pair quad; values (i&1)*2 + {0,1}
            e[4] = __shfl_sync(FULL, eq[qp], 8 * (i & 1), 16);
            e[5] = __shfl_sync(FULL, eq[qp], 8 * (i & 1) + 4, 16);
        }
        float sum = 0.f;
        float4 acc = make_float4(0.f, 0.f, 0.f, 0.f);
#pragma unroll
        for (int j = 0; j < 6; j++) {
            sum += e[j];
            acc.x = fmaf(e[j], vr[j].x, acc.x);
            acc.y = fmaf(e[j], vr[j].y, acc.y);
            acc.z = fmaf(e[j], vr[j].z, acc.z);
            acc.w = fmaf(e[j], vr[j].w, acc.w);
        }
        const float inv = __frcp_rn(sum);
        acc.x *= inv; acc.y *= inv; acc.z *= inv; acc.w *= inv;
        *reinterpret_cast<float4*>(O + o[i]) = acc;
    }
}

extern "C" void kernel_launch(void* const* d_in, const int* in_sizes, int n_in,
                              void* d_out, int out_size)
{
    const float* Q = (const float*)d_in[0];
    const float* K = (const float*)d_in[1];
    const float* V = (const float*)d_in[2];
    float* O = (float*)d_out;

    const int total_groups = Bq * Vq * Hq * NGROUPS;              // 65536
    const int blocks = total_groups / (2 * WARPS_PER_BLOCK);      // 4096
    neighbour_attn_kernel<<<blocks, WARPS_PER_BLOCK * 32>>>(Q, K, V, O);
}